// round 10
// baseline (speedup 1.0000x reference)
#include <cuda_runtime.h>
#include <math.h>

#define N_NODES 100000
#define N_EDGES 3200000
#define F_IN    256
#define U       32
#define C       40

#define SCAN_CH   512
#define SCAN_NB   ((N_NODES + SCAN_CH - 1) / SCAN_CH)   // 196

#define TILE_N 64
#define KT     64
#define XSTR   66                                    // even: float2-aligned reads, 2-way STS conflict only
#define N_TILES      ((N_NODES + TILE_N - 1) / TILE_N)  // 1563
#define INV_TILES    300
#define INV_HOST     ((N_NODES + 255) / 256)            // 391
#define REO_TILES    (N_TILES - INV_TILES)              // 1263
#define REO_HOST     ((N_EDGES + 255) / 256)            // 12500

// ---- scratch (device globals; no allocations allowed) ----
__device__ int   g_degout_i[N_NODES];
__device__ int   g_degin_i[N_NODES];
__device__ float g_invout[N_NODES];
__device__ float g_invin[N_NODES];
__device__ int   g_part[SCAN_NB];
__device__ int   g_off[N_NODES + 1];
__device__ int   g_cursor[N_NODES];
__device__ int   g_esrc[N_EDGES];
__device__ float g_h1[(size_t)N_NODES * U];   // (x * d_out^-1/2) @ W1
__device__ float g_h2[(size_t)N_NODES * C];   // (relu(L1 out) * d_out^-1/2) @ W2

// ---------------------------------------------------------------------------
__global__ void zero_deg_kernel() {
    int i = blockIdx.x * blockDim.x + threadIdx.x;
    if (i < N_NODES) { g_degout_i[i] = 0; g_degin_i[i] = 0; }
}

__global__ void hist_kernel(const int* __restrict__ src, const int* __restrict__ dst) {
    int e = blockIdx.x * blockDim.x + threadIdx.x;
    if (e >= N_EDGES) return;
    atomicAdd(&g_degout_i[src[e]], 1);
    atomicAdd(&g_degin_i[dst[e]], 1);
}

// ---------------------------------------------------------------------------
// GEMM1 tile (256 threads): h1[n,u] = rsqrt(max(degout,1)) * sum_k x[n,k]*W1[k,u]
// Depends ONLY on hist (computes its own rsqrt) -> can run concurrently with
// the invsqrt/scan/reorder chain. 64-node x 32-u tile, 2x4 accum per thread.
__device__ __forceinline__ void gemm1_tile(int tile, const float* __restrict__ x,
                                           const float* __restrict__ W1) {
    __shared__ float sXT[KT * XSTR];
    __shared__ float sW[KT][U];

    const int t  = threadIdx.x;
    const int ug = t & 7;        // u-group of 4
    const int ng = t >> 3;       // 0..31 -> nodes 2*ng, 2*ng+1
    const int n0 = tile * TILE_N;

    float acc[2][4] = {};

    for (int k0 = 0; k0 < F_IN; k0 += KT) {
        for (int i = t; i < KT * U; i += 256)
            ((float*)sW)[i] = W1[k0 * U + i];
        for (int i = t; i < TILE_N * KT; i += 256) {
            int n = i >> 6;            // node in tile
            int k = i & (KT - 1);      // consecutive k per consecutive thread -> coalesced LDG
            int gn = n0 + n;
            sXT[k * XSTR + n] = (gn < N_NODES) ? x[(size_t)gn * F_IN + k0 + k] : 0.f;
        }
        __syncthreads();
#pragma unroll
        for (int k = 0; k < KT; k++) {
            float4 w  = *(const float4*)&sW[k][ug * 4];
            float2 xv = *(const float2*)&sXT[k * XSTR + ng * 2];
            acc[0][0] += xv.x * w.x; acc[0][1] += xv.x * w.y;
            acc[0][2] += xv.x * w.z; acc[0][3] += xv.x * w.w;
            acc[1][0] += xv.y * w.x; acc[1][1] += xv.y * w.y;
            acc[1][2] += xv.y * w.z; acc[1][3] += xv.y * w.w;
        }
        __syncthreads();
    }

#pragma unroll
    for (int i = 0; i < 2; i++) {
        int n = n0 + ng * 2 + i;
        if (n < N_NODES) {
            float s = rsqrtf(fmaxf((float)g_degout_i[n], 1.0f));
            float4 o;
            o.x = acc[i][0] * s; o.y = acc[i][1] * s;
            o.z = acc[i][2] * s; o.w = acc[i][3] * s;
            *(float4*)&g_h1[(size_t)n * U + ug * 4] = o;
        }
    }
}

// invsqrt host + gemm tiles [0, INV_TILES)
__global__ void __launch_bounds__(256) invsqrt_gemm_kernel(const float* __restrict__ x,
                                                           const float* __restrict__ W1) {
    if (blockIdx.x < INV_HOST) {
        int n = blockIdx.x * 256 + threadIdx.x;
        if (n < N_NODES) {
            g_invout[n] = rsqrtf(fmaxf((float)g_degout_i[n], 1.0f));
            g_invin[n]  = rsqrtf(fmaxf((float)g_degin_i[n],  1.0f));
        }
    } else {
        gemm1_tile(blockIdx.x - INV_HOST, x, W1);
    }
}

// reorder host + gemm tiles [INV_TILES, N_TILES)
__global__ void __launch_bounds__(256) reorder_gemm_kernel(const int* __restrict__ src,
                                                           const int* __restrict__ dst,
                                                           const float* __restrict__ x,
                                                           const float* __restrict__ W1) {
    if (blockIdx.x < REO_HOST) {
        int e = blockIdx.x * 256 + threadIdx.x;
        if (e < N_EDGES) {
            int pos = atomicAdd(&g_cursor[dst[e]], 1);
            g_esrc[pos] = src[e];
        }
    } else {
        gemm1_tile(INV_TILES + (blockIdx.x - REO_HOST), x, W1);
    }
}

// ---------------------------------------------------------------------------
__global__ void __launch_bounds__(SCAN_CH) scan_part_kernel() {
    __shared__ int sw[SCAN_CH / 32];
    const int t = threadIdx.x;
    const int i = blockIdx.x * SCAN_CH + t;
    int v = (i < N_NODES) ? g_degin_i[i] : 0;
#pragma unroll
    for (int o = 16; o; o >>= 1) v += __shfl_xor_sync(0xffffffffu, v, o);
    if ((t & 31) == 0) sw[t >> 5] = v;
    __syncthreads();
    if (t < SCAN_CH / 32) {
        int s = sw[t];
#pragma unroll
        for (int o = SCAN_CH / 64; o; o >>= 1) s += __shfl_xor_sync(0xffffffffu, s, o);
        if (t == 0) g_part[blockIdx.x] = s;
    }
}

__global__ void scan_mid_kernel() {
    __shared__ int s[256];
    const int t = threadIdx.x;
    int v = (t < SCAN_NB) ? g_part[t] : 0;
    s[t] = v;
    __syncthreads();
#pragma unroll
    for (int off = 1; off < 256; off <<= 1) {
        int u = (t >= off) ? s[t - off] : 0;
        __syncthreads();
        s[t] += u;
        __syncthreads();
    }
    if (t < SCAN_NB) g_part[t] = s[t] - v;
}

__global__ void __launch_bounds__(SCAN_CH) scan_write_kernel() {
    __shared__ int s[SCAN_CH];
    const int t = threadIdx.x;
    const int i = blockIdx.x * SCAN_CH + t;
    int v = (i < N_NODES) ? g_degin_i[i] : 0;
    s[t] = v;
    __syncthreads();
#pragma unroll
    for (int off = 1; off < SCAN_CH; off <<= 1) {
        int u = (t >= off) ? s[t - off] : 0;
        __syncthreads();
        s[t] += u;
        __syncthreads();
    }
    if (i < N_NODES) {
        int off = g_part[blockIdx.x] + s[t] - v;
        g_off[i] = off;
        g_cursor[i] = off;
    }
    if (i == 0) g_off[N_NODES] = N_EDGES;
}

// ---------------------------------------------------------------------------
// Aggregation layer 1 + relu + GEMM2, fused (R8-proven structure).
__global__ void __launch_bounds__(256) agg1_kernel(const float* __restrict__ b1,
                                                   const float* __restrict__ W2) {
    __shared__ float sW2[U * C];
    for (int i = threadIdx.x; i < U * C; i += 256) sW2[i] = W2[i];
    __syncthreads();

    const int n = (blockIdx.x * blockDim.x + threadIdx.x) >> 5;
    const int lane = threadIdx.x & 31;
    if (n >= N_NODES) return;
    const int start = g_off[n], end = g_off[n + 1];

    float acc = 0.f;
    int e = start;
    while (e + 32 <= end) {
        int sv = g_esrc[e + lane];
        float a0 = 0.f, a1 = 0.f, a2 = 0.f, a3 = 0.f;
#pragma unroll
        for (int i = 0; i < 32; i += 4) {
            int s0 = __shfl_sync(0xffffffffu, sv, i);
            int s1 = __shfl_sync(0xffffffffu, sv, i + 1);
            int s2 = __shfl_sync(0xffffffffu, sv, i + 2);
            int s3 = __shfl_sync(0xffffffffu, sv, i + 3);
            a0 += g_h1[(size_t)s0 * U + lane];
            a1 += g_h1[(size_t)s1 * U + lane];
            a2 += g_h1[(size_t)s2 * U + lane];
            a3 += g_h1[(size_t)s3 * U + lane];
        }
        acc += (a0 + a1) + (a2 + a3);
        e += 32;
    }
    if (e < end) {
        int rem = end - e;
        int sv = (lane < rem) ? g_esrc[e + lane] : 0;
        for (int i = 0; i < rem; i++) {
            int s = __shfl_sync(0xffffffffu, sv, i);
            acc += g_h1[(size_t)s * U + lane];
        }
    }

    const float v = fmaxf(acc * g_invin[n] + b1[lane], 0.f);

    float o0 = 0.f, o1 = 0.f;
#pragma unroll
    for (int k = 0; k < U; k++) {
        float h = __shfl_sync(0xffffffffu, v, k);
        o0 += h * sW2[k * C + lane];
        if (lane < 8) o1 += h * sW2[k * C + 32 + lane];
    }
    const float so = g_invout[n];
    g_h2[(size_t)n * C + lane] = o0 * so;
    if (lane < 8) g_h2[(size_t)n * C + 32 + lane] = o1 * so;
}

// ---------------------------------------------------------------------------
// Aggregation layer 2: float2 gather on lanes 0-19 (one LDG.64 per edge)
// + norm + bias + log_softmax -> d_out.
__global__ void agg2_kernel(float* __restrict__ out, const float* __restrict__ b2) {
    const int n = (blockIdx.x * blockDim.x + threadIdx.x) >> 5;
    const int lane = threadIdx.x & 31;
    if (n >= N_NODES) return;
    const int start = g_off[n], end = g_off[n + 1];
    const bool act = lane < 20;

    float ax = 0.f, ay = 0.f;
    int e = start;
    while (e + 32 <= end) {
        int sv = g_esrc[e + lane];
#pragma unroll
        for (int i = 0; i < 32; i++) {
            int s = __shfl_sync(0xffffffffu, sv, i);
            if (act) {
                float2 v = *(const float2*)&g_h2[(size_t)s * C + 2 * lane];
                ax += v.x; ay += v.y;
            }
        }
        e += 32;
    }
    if (e < end) {
        int rem = end - e;
        int sv = (lane < rem) ? g_esrc[e + lane] : 0;
        for (int i = 0; i < rem; i++) {
            int s = __shfl_sync(0xffffffffu, sv, i);
            if (act) {
                float2 v = *(const float2*)&g_h2[(size_t)s * C + 2 * lane];
                ax += v.x; ay += v.y;
            }
        }
    }

    const float inv = g_invin[n];
    const float NEG_INF = __int_as_float(0xff800000);
    float v0 = act ? (ax * inv + b2[2 * lane])     : NEG_INF;
    float v1 = act ? (ay * inv + b2[2 * lane + 1]) : NEG_INF;

    float m = fmaxf(v0, v1);
#pragma unroll
    for (int o = 16; o; o >>= 1) m = fmaxf(m, __shfl_xor_sync(0xffffffffu, m, o));
    float se = act ? (expf(v0 - m) + expf(v1 - m)) : 0.f;
#pragma unroll
    for (int o = 16; o; o >>= 1) se += __shfl_xor_sync(0xffffffffu, se, o);
    const float ls = logf(se);

    if (act) {
        float2 o;
        o.x = v0 - m - ls;
        o.y = v1 - m - ls;
        *(float2*)&out[(size_t)n * C + 2 * lane] = o;
    }
}

// ---------------------------------------------------------------------------
extern "C" void kernel_launch(void* const* d_in, const int* in_sizes, int n_in,
                              void* d_out, int out_size) {
    const float* x   = (const float*)d_in[0];
    const float* W1  = (const float*)d_in[1];
    const float* b1  = (const float*)d_in[2];
    const float* W2  = (const float*)d_in[3];
    const float* b2  = (const float*)d_in[4];
    const int*   src = (const int*)d_in[5];
    const int*   dst = (const int*)d_in[6];
    float* out = (float*)d_out;

    zero_deg_kernel<<<(N_NODES + 255) / 256, 256>>>();
    hist_kernel<<<(N_EDGES + 255) / 256, 256>>>(src, dst);
    invsqrt_gemm_kernel<<<INV_HOST + INV_TILES, 256>>>(x, W1);     // invsqrt || gemm tiles
    scan_part_kernel<<<SCAN_NB, SCAN_CH>>>();
    scan_mid_kernel<<<1, 256>>>();
    scan_write_kernel<<<SCAN_NB, SCAN_CH>>>();
    reorder_gemm_kernel<<<REO_HOST + REO_TILES, 256>>>(src, dst, x, W1);  // reorder || gemm tiles
    agg1_kernel<<<(N_NODES * 32 + 255) / 256, 256>>>(b1, W2);
    agg2_kernel<<<(N_NODES * 32 + 255) / 256, 256>>>(out, b2);
}

// round 11
// speedup vs baseline: 1.0853x; 1.0853x over previous
#include <cuda_runtime.h>
#include <math.h>

#define N_NODES 100000
#define N_EDGES 3200000
#define F_IN    256
#define U       32
#define C       40

#define SCAN_CH   512
#define SCAN_NB   ((N_NODES + SCAN_CH - 1) / SCAN_CH)   // 196

// ---- scratch (device globals; no allocations allowed) ----
__device__ int   g_degout_i[N_NODES];
__device__ int   g_degin_i[N_NODES];
__device__ float g_invout[N_NODES];
__device__ float g_invin[N_NODES];
__device__ int   g_part[SCAN_NB];
__device__ int   g_off[N_NODES + 1];
__device__ int   g_cursor[N_NODES];
__device__ int   g_esrc[N_EDGES];
__device__ __align__(16) float g_h1[(size_t)N_NODES * U];   // (x * d_out^-1/2) @ W1
__device__ __align__(16) float g_h2[(size_t)N_NODES * C];   // (relu(L1) * d_out^-1/2) @ W2

// ---------------------------------------------------------------------------
__global__ void zero_deg_kernel() {
    int i = blockIdx.x * blockDim.x + threadIdx.x;
    if (i < N_NODES) { g_degout_i[i] = 0; g_degin_i[i] = 0; }
}

__global__ void hist_kernel(const int* __restrict__ src, const int* __restrict__ dst) {
    int e = blockIdx.x * blockDim.x + threadIdx.x;
    if (e >= N_EDGES) return;
    atomicAdd(&g_degout_i[src[e]], 1);
    atomicAdd(&g_degin_i[dst[e]], 1);
}

__global__ void invsqrt_kernel() {
    int n = blockIdx.x * blockDim.x + threadIdx.x;
    if (n >= N_NODES) return;
    g_invout[n] = rsqrtf(fmaxf((float)g_degout_i[n], 1.0f));
    g_invin[n]  = rsqrtf(fmaxf((float)g_degin_i[n],  1.0f));
}

// ---------------------------------------------------------------------------
// GEMM1 (R9 variant, measured 77.5us): 64-node x 32-u tile, 128 threads,
// 4x4 per thread, transposed x tile -> 2x LDS.128 per 16 FFMA.
#define TILE_N 64
#define KT     64
#define XSTR   (TILE_N + 4)    // 68 floats: 16B-aligned rows, bank-shift 4
__global__ void __launch_bounds__(128) gemm1_kernel(const float* __restrict__ x,
                                                    const float* __restrict__ W1) {
    __shared__ float sXT[KT * XSTR];
    __shared__ float sW[KT][U];

    const int t  = threadIdx.x;
    const int ug = t & 7;
    const int ng = t >> 3;
    const int n0 = blockIdx.x * TILE_N;

    float acc[4][4] = {};

    for (int k0 = 0; k0 < F_IN; k0 += KT) {
        for (int i = t; i < KT * U; i += 128)
            ((float*)sW)[i] = W1[k0 * U + i];
        for (int i = t; i < TILE_N * KT; i += 128) {
            int n = i >> 6;
            int k = i & (KT - 1);
            int gn = n0 + n;
            sXT[k * XSTR + n] = (gn < N_NODES) ? x[(size_t)gn * F_IN + k0 + k] : 0.f;
        }
        __syncthreads();
#pragma unroll
        for (int k = 0; k < KT; k++) {
            float4 w  = *(const float4*)&sW[k][ug * 4];
            float4 xv = *(const float4*)&sXT[k * XSTR + ng * 4];
            acc[0][0] += xv.x * w.x; acc[0][1] += xv.x * w.y; acc[0][2] += xv.x * w.z; acc[0][3] += xv.x * w.w;
            acc[1][0] += xv.y * w.x; acc[1][1] += xv.y * w.y; acc[1][2] += xv.y * w.z; acc[1][3] += xv.y * w.w;
            acc[2][0] += xv.z * w.x; acc[2][1] += xv.z * w.y; acc[2][2] += xv.z * w.z; acc[2][3] += xv.z * w.w;
            acc[3][0] += xv.w * w.x; acc[3][1] += xv.w * w.y; acc[3][2] += xv.w * w.z; acc[3][3] += xv.w * w.w;
        }
        __syncthreads();
    }

#pragma unroll
    for (int i = 0; i < 4; i++) {
        int n = n0 + ng * 4 + i;
        if (n < N_NODES) {
            float s = g_invout[n];
            float4 o;
            o.x = acc[i][0] * s; o.y = acc[i][1] * s;
            o.z = acc[i][2] * s; o.w = acc[i][3] * s;
            *(float4*)&g_h1[(size_t)n * U + ug * 4] = o;
        }
    }
}

// ---------------------------------------------------------------------------
__global__ void __launch_bounds__(SCAN_CH) scan_part_kernel() {
    __shared__ int sw[SCAN_CH / 32];
    const int t = threadIdx.x;
    const int i = blockIdx.x * SCAN_CH + t;
    int v = (i < N_NODES) ? g_degin_i[i] : 0;
#pragma unroll
    for (int o = 16; o; o >>= 1) v += __shfl_xor_sync(0xffffffffu, v, o);
    if ((t & 31) == 0) sw[t >> 5] = v;
    __syncthreads();
    if (t < SCAN_CH / 32) {
        int s = sw[t];
#pragma unroll
        for (int o = SCAN_CH / 64; o; o >>= 1) s += __shfl_xor_sync(0xffffffffu, s, o);
        if (t == 0) g_part[blockIdx.x] = s;
    }
}

__global__ void scan_mid_kernel() {
    __shared__ int s[256];
    const int t = threadIdx.x;
    int v = (t < SCAN_NB) ? g_part[t] : 0;
    s[t] = v;
    __syncthreads();
#pragma unroll
    for (int off = 1; off < 256; off <<= 1) {
        int u = (t >= off) ? s[t - off] : 0;
        __syncthreads();
        s[t] += u;
        __syncthreads();
    }
    if (t < SCAN_NB) g_part[t] = s[t] - v;
}

__global__ void __launch_bounds__(SCAN_CH) scan_write_kernel() {
    __shared__ int s[SCAN_CH];
    const int t = threadIdx.x;
    const int i = blockIdx.x * SCAN_CH + t;
    int v = (i < N_NODES) ? g_degin_i[i] : 0;
    s[t] = v;
    __syncthreads();
#pragma unroll
    for (int off = 1; off < SCAN_CH; off <<= 1) {
        int u = (t >= off) ? s[t - off] : 0;
        __syncthreads();
        s[t] += u;
        __syncthreads();
    }
    if (i < N_NODES) {
        int off = g_part[blockIdx.x] + s[t] - v;
        g_off[i] = off;
        g_cursor[i] = off;
    }
    if (i == 0) g_off[N_NODES] = N_EDGES;
}

__global__ void reorder_kernel(const int* __restrict__ src, const int* __restrict__ dst) {
    int e = blockIdx.x * blockDim.x + threadIdx.x;
    if (e >= N_EDGES) return;
    int pos = atomicAdd(&g_cursor[dst[e]], 1);
    g_esrc[pos] = src[e];
}

// ---------------------------------------------------------------------------
// Aggregation layer 1 + relu + GEMM2, fused.
// One warp per node. lane = (slot = lane>>3 in 0..3, q = lane&7): 4 edges per
// step, each lane loads float4 of features 4q..4q+3 -> 1.5 instr/edge.
__global__ void __launch_bounds__(256) agg1_kernel(const float* __restrict__ b1,
                                                   const float* __restrict__ W2) {
    __shared__ float sW2[U * C];
    for (int i = threadIdx.x; i < U * C; i += 256) sW2[i] = W2[i];
    __syncthreads();

    const int n = (blockIdx.x * blockDim.x + threadIdx.x) >> 5;
    const int lane = threadIdx.x & 31;
    if (n >= N_NODES) return;
    const int slot = lane >> 3;     // edge slot 0..3
    const int q    = lane & 7;      // feature quad
    const int start = g_off[n], end = g_off[n + 1];

    float4 a4 = make_float4(0.f, 0.f, 0.f, 0.f);
    int e = start;
    while (e + 32 <= end) {
        int sv = g_esrc[e + lane];
#pragma unroll
        for (int i = 0; i < 8; i++) {
            int s = __shfl_sync(0xffffffffu, sv, 4 * i + slot);
            float4 v = *(const float4*)&g_h1[(size_t)s * U + 4 * q];
            a4.x += v.x; a4.y += v.y; a4.z += v.z; a4.w += v.w;
        }
        e += 32;
    }
    if (e < end) {
        const int rem = end - e;                      // 1..31
        const int idx = e + lane;
        int sv = g_esrc[idx < end ? idx : end - 1];
        const int steps = (rem + 3) >> 2;
        for (int i = 0; i < steps; i++) {
            int s = __shfl_sync(0xffffffffu, sv, 4 * i + slot);
            float4 v = *(const float4*)&g_h1[(size_t)s * U + 4 * q];
            if (4 * i + slot < rem) { a4.x += v.x; a4.y += v.y; a4.z += v.z; a4.w += v.w; }
        }
    }
    // reduce across the 4 edge slots (lanes q, q+8, q+16, q+24)
#pragma unroll
    for (int o = 8; o <= 16; o <<= 1) {
        a4.x += __shfl_xor_sync(0xffffffffu, a4.x, o);
        a4.y += __shfl_xor_sync(0xffffffffu, a4.y, o);
        a4.z += __shfl_xor_sync(0xffffffffu, a4.z, o);
        a4.w += __shfl_xor_sync(0xffffffffu, a4.w, o);
    }

    // redistribute: lane needs feature 'lane' = quad (lane>>2), comp (lane&3)
    const int srcl = lane >> 2;
    float cx = __shfl_sync(0xffffffffu, a4.x, srcl);
    float cy = __shfl_sync(0xffffffffu, a4.y, srcl);
    float cz = __shfl_sync(0xffffffffu, a4.z, srcl);
    float cw = __shfl_sync(0xffffffffu, a4.w, srcl);
    const int comp = lane & 3;
    float accf = (comp == 0) ? cx : (comp == 1) ? cy : (comp == 2) ? cz : cw;

    // relu(norm + bias)
    const float v = fmaxf(accf * g_invin[n] + b1[lane], 0.f);

    // fused gemm2: h2[n,j] = invout[n] * sum_k v[k] * W2[k,j]
    float o0 = 0.f, o1 = 0.f;
#pragma unroll
    for (int k = 0; k < U; k++) {
        float h = __shfl_sync(0xffffffffu, v, k);
        o0 += h * sW2[k * C + lane];
        if (lane < 8) o1 += h * sW2[k * C + 32 + lane];
    }
    const float so = g_invout[n];
    g_h2[(size_t)n * C + lane] = o0 * so;
    if (lane < 8) g_h2[(size_t)n * C + 32 + lane] = o1 * so;
}

// ---------------------------------------------------------------------------
// Aggregation layer 2: float2 gather on lanes 0-19 (1 LDG.64/edge)
// + norm + bias + log_softmax -> d_out.
__global__ void agg2_kernel(float* __restrict__ out, const float* __restrict__ b2) {
    const int n = (blockIdx.x * blockDim.x + threadIdx.x) >> 5;
    const int lane = threadIdx.x & 31;
    if (n >= N_NODES) return;
    const int start = g_off[n], end = g_off[n + 1];
    const bool act = lane < 20;

    float ax = 0.f, ay = 0.f;
    int e = start;
    while (e + 32 <= end) {
        int sv = g_esrc[e + lane];
#pragma unroll
        for (int i = 0; i < 32; i++) {
            int s = __shfl_sync(0xffffffffu, sv, i);
            if (act) {
                float2 v = *(const float2*)&g_h2[(size_t)s * C + 2 * lane];
                ax += v.x; ay += v.y;
            }
        }
        e += 32;
    }
    if (e < end) {
        int rem = end - e;
        int sv = (lane < rem) ? g_esrc[e + lane] : 0;
        for (int i = 0; i < rem; i++) {
            int s = __shfl_sync(0xffffffffu, sv, i);
            if (act) {
                float2 v = *(const float2*)&g_h2[(size_t)s * C + 2 * lane];
                ax += v.x; ay += v.y;
            }
        }
    }

    const float inv = g_invin[n];
    const float NEG_INF = __int_as_float(0xff800000);
    float v0 = act ? (ax * inv + b2[2 * lane])     : NEG_INF;
    float v1 = act ? (ay * inv + b2[2 * lane + 1]) : NEG_INF;

    float m = fmaxf(v0, v1);
#pragma unroll
    for (int o = 16; o; o >>= 1) m = fmaxf(m, __shfl_xor_sync(0xffffffffu, m, o));
    float se = act ? (expf(v0 - m) + expf(v1 - m)) : 0.f;
#pragma unroll
    for (int o = 16; o; o >>= 1) se += __shfl_xor_sync(0xffffffffu, se, o);
    const float ls = logf(se);

    if (act) {
        float2 o;
        o.x = v0 - m - ls;
        o.y = v1 - m - ls;
        *(float2*)&out[(size_t)n * C + 2 * lane] = o;
    }
}

// ---------------------------------------------------------------------------
extern "C" void kernel_launch(void* const* d_in, const int* in_sizes, int n_in,
                              void* d_out, int out_size) {
    const float* x   = (const float*)d_in[0];
    const float* W1  = (const float*)d_in[1];
    const float* b1  = (const float*)d_in[2];
    const float* W2  = (const float*)d_in[3];
    const float* b2  = (const float*)d_in[4];
    const int*   src = (const int*)d_in[5];
    const int*   dst = (const int*)d_in[6];
    float* out = (float*)d_out;

    zero_deg_kernel<<<(N_NODES + 255) / 256, 256>>>();
    hist_kernel<<<(N_EDGES + 255) / 256, 256>>>(src, dst);
    invsqrt_kernel<<<(N_NODES + 255) / 256, 256>>>();
    gemm1_kernel<<<(N_NODES + TILE_N - 1) / TILE_N, 128>>>(x, W1);   // slot #4 -> profiled
    scan_part_kernel<<<SCAN_NB, SCAN_CH>>>();
    scan_mid_kernel<<<1, 256>>>();
    scan_write_kernel<<<SCAN_NB, SCAN_CH>>>();
    reorder_kernel<<<(N_EDGES + 255) / 256, 256>>>(src, dst);
    agg1_kernel<<<(N_NODES * 32 + 255) / 256, 256>>>(b1, W2);
    agg2_kernel<<<(N_NODES * 32 + 255) / 256, 256>>>(out, b2);
}

// round 12
// speedup vs baseline: 1.1285x; 1.0398x over previous
#include <cuda_runtime.h>
#include <math.h>

#define N_NODES 100000
#define N_EDGES 3200000
#define F_IN    256
#define U       32
#define C       40

#define SCAN_CH   512
#define SCAN_NB   ((N_NODES + SCAN_CH - 1) / SCAN_CH)   // 196

// ---- scratch (device globals; no allocations allowed) ----
__device__ int   g_degout_i[N_NODES];
__device__ int   g_degin_i[N_NODES];
__device__ float g_invout[N_NODES];
__device__ float g_invin[N_NODES];
__device__ int   g_part[SCAN_NB];
__device__ int   g_off[N_NODES + 1];
__device__ int   g_cursor[N_NODES];
__device__ int   g_esrc[N_EDGES];
__device__ __align__(16) float g_h1[(size_t)N_NODES * U];   // (x * d_out^-1/2) @ W1
__device__ __align__(16) float g_h2[(size_t)N_NODES * C];   // (relu(L1) * d_out^-1/2) @ W2

// ---------------------------------------------------------------------------
__global__ void zero_deg_kernel() {
    int i = blockIdx.x * blockDim.x + threadIdx.x;
    if (i < N_NODES) { g_degout_i[i] = 0; g_degin_i[i] = 0; }
}

__global__ void hist_kernel(const int* __restrict__ src, const int* __restrict__ dst) {
    int e = blockIdx.x * blockDim.x + threadIdx.x;
    if (e >= N_EDGES) return;
    atomicAdd(&g_degout_i[src[e]], 1);
    atomicAdd(&g_degin_i[dst[e]], 1);
}

__global__ void invsqrt_kernel() {
    int n = blockIdx.x * blockDim.x + threadIdx.x;
    if (n >= N_NODES) return;
    g_invout[n] = rsqrtf(fmaxf((float)g_degout_i[n], 1.0f));
    g_invin[n]  = rsqrtf(fmaxf((float)g_degin_i[n],  1.0f));
}

// ---------------------------------------------------------------------------
// GEMM1 via tf32 tensor cores with hi/lo split (fp32-grade accuracy).
// Block = 128 threads (4 warps), tile = 64 nodes x 32 u, K chunks of 32.
// Each warp owns 16 rows; 4 n-tiles of 8; mma.m16n8k8: D += Ah*Bh + Al*Bh + Ah*Bl.
#define TILE_N 64
#define KT2    32
#define ASTR   36     // a-frag LDS bank = (4r + c) % 32 -> conflict-free
#define BSTR   40     // b-frag LDS bank = (8k + n) % 32 -> conflict-free

__device__ __forceinline__ unsigned f2tf(float f) {
    unsigned r; asm("cvt.rna.tf32.f32 %0, %1;" : "=r"(r) : "f"(f)); return r;
}
__device__ __forceinline__ void mma_tf32(float* d, const unsigned* a, const unsigned* b) {
    asm("mma.sync.aligned.m16n8k8.row.col.f32.tf32.tf32.f32 "
        "{%0,%1,%2,%3}, {%4,%5,%6,%7}, {%8,%9}, {%0,%1,%2,%3};"
        : "+f"(d[0]), "+f"(d[1]), "+f"(d[2]), "+f"(d[3])
        : "r"(a[0]), "r"(a[1]), "r"(a[2]), "r"(a[3]), "r"(b[0]), "r"(b[1]));
}

__global__ void __launch_bounds__(128) gemm1_kernel(const float* __restrict__ x,
                                                    const float* __restrict__ W1) {
    __shared__ unsigned sAh[TILE_N * ASTR];
    __shared__ unsigned sAl[TILE_N * ASTR];
    __shared__ unsigned sBh[KT2 * BSTR];
    __shared__ unsigned sBl[KT2 * BSTR];

    const int t = threadIdx.x;
    const int warp = t >> 5, lane = t & 31;
    const int n0blk = blockIdx.x * TILE_N;
    const int r = lane >> 2, c = lane & 3;    // a-frag / d-frag coords
    const int m0 = warp * 16;

    float d[4][4] = {};    // [n-tile][frag]

    for (int k0 = 0; k0 < F_IN; k0 += KT2) {
        // ---- stage x tile (64 x 32) as tf32 hi/lo ----
        for (int i = t; i < TILE_N * (KT2 / 4); i += 128) {   // 512 float4s
            int row = i >> 3, c4 = i & 7;
            int gn = n0blk + row;
            float4 v = make_float4(0.f, 0.f, 0.f, 0.f);
            if (gn < N_NODES) v = *(const float4*)&x[(size_t)gn * F_IN + k0 + c4 * 4];
            unsigned h0 = f2tf(v.x), h1 = f2tf(v.y), h2 = f2tf(v.z), h3 = f2tf(v.w);
            float4 hf = make_float4(__uint_as_float(h0), __uint_as_float(h1),
                                    __uint_as_float(h2), __uint_as_float(h3));
            unsigned l0 = f2tf(v.x - hf.x), l1 = f2tf(v.y - hf.y);
            unsigned l2 = f2tf(v.z - hf.z), l3 = f2tf(v.w - hf.w);
            uint4 hv = make_uint4(h0, h1, h2, h3);
            uint4 lv = make_uint4(l0, l1, l2, l3);
            *(uint4*)&sAh[row * ASTR + c4 * 4] = hv;   // row*36*4B is 16B-aligned
            *(uint4*)&sAl[row * ASTR + c4 * 4] = lv;
        }
        // ---- stage W1 tile (32 x 32) as tf32 hi/lo ----
        for (int i = t; i < KT2 * (U / 4); i += 128) {        // 256 float4s
            int k = i >> 3, c4 = i & 7;
            float4 v = *(const float4*)&W1[(size_t)(k0 + k) * U + c4 * 4];
            unsigned h0 = f2tf(v.x), h1 = f2tf(v.y), h2 = f2tf(v.z), h3 = f2tf(v.w);
            float4 hf = make_float4(__uint_as_float(h0), __uint_as_float(h1),
                                    __uint_as_float(h2), __uint_as_float(h3));
            unsigned l0 = f2tf(v.x - hf.x), l1 = f2tf(v.y - hf.y);
            unsigned l2 = f2tf(v.z - hf.z), l3 = f2tf(v.w - hf.w);
            uint4 hv = make_uint4(h0, h1, h2, h3);
            uint4 lv = make_uint4(l0, l1, l2, l3);
            *(uint4*)&sBh[k * BSTR + c4 * 4] = hv;     // k*40*4B is 16B-aligned
            *(uint4*)&sBl[k * BSTR + c4 * 4] = lv;
        }
        __syncthreads();

#pragma unroll
        for (int ks = 0; ks < KT2 / 8; ks++) {
            const int kk = ks * 8;
            unsigned ah[4], al[4];
            const int abase = (m0 + r) * ASTR + kk + c;
            ah[0] = sAh[abase];            ah[1] = sAh[abase + 8 * ASTR];
            ah[2] = sAh[abase + 4];        ah[3] = sAh[abase + 8 * ASTR + 4];
            al[0] = sAl[abase];            al[1] = sAl[abase + 8 * ASTR];
            al[2] = sAl[abase + 4];        al[3] = sAl[abase + 8 * ASTR + 4];
#pragma unroll
            for (int nt = 0; nt < 4; nt++) {
                unsigned bh[2], bl[2];
                const int bbase = (kk + c) * BSTR + nt * 8 + r;   // b: k=c(lane%4), n=r(lane>>2)
                bh[0] = sBh[bbase];            bh[1] = sBh[bbase + 4 * BSTR];
                bl[0] = sBl[bbase];            bl[1] = sBl[bbase + 4 * BSTR];
                mma_tf32(d[nt], ah, bh);
                mma_tf32(d[nt], al, bh);
                mma_tf32(d[nt], ah, bl);
            }
        }
        __syncthreads();
    }

    // ---- epilogue: scale by invout, write 2 rows x 4 n-tiles as float2 ----
    const int n1 = n0blk + m0 + r;
    const int n2 = n1 + 8;
    const float s1 = (n1 < N_NODES) ? g_invout[n1] : 0.f;
    const float s2 = (n2 < N_NODES) ? g_invout[n2] : 0.f;
#pragma unroll
    for (int nt = 0; nt < 4; nt++) {
        const int u = nt * 8 + c * 2;
        if (n1 < N_NODES) {
            float2 o; o.x = d[nt][0] * s1; o.y = d[nt][1] * s1;
            *(float2*)&g_h1[(size_t)n1 * U + u] = o;
        }
        if (n2 < N_NODES) {
            float2 o; o.x = d[nt][2] * s2; o.y = d[nt][3] * s2;
            *(float2*)&g_h1[(size_t)n2 * U + u] = o;
        }
    }
}

// ---------------------------------------------------------------------------
__global__ void __launch_bounds__(SCAN_CH) scan_part_kernel() {
    __shared__ int sw[SCAN_CH / 32];
    const int t = threadIdx.x;
    const int i = blockIdx.x * SCAN_CH + t;
    int v = (i < N_NODES) ? g_degin_i[i] : 0;
#pragma unroll
    for (int o = 16; o; o >>= 1) v += __shfl_xor_sync(0xffffffffu, v, o);
    if ((t & 31) == 0) sw[t >> 5] = v;
    __syncthreads();
    if (t < SCAN_CH / 32) {
        int s = sw[t];
#pragma unroll
        for (int o = SCAN_CH / 64; o; o >>= 1) s += __shfl_xor_sync(0xffffffffu, s, o);
        if (t == 0) g_part[blockIdx.x] = s;
    }
}

__global__ void scan_mid_kernel() {
    __shared__ int s[256];
    const int t = threadIdx.x;
    int v = (t < SCAN_NB) ? g_part[t] : 0;
    s[t] = v;
    __syncthreads();
#pragma unroll
    for (int off = 1; off < 256; off <<= 1) {
        int u = (t >= off) ? s[t - off] : 0;
        __syncthreads();
        s[t] += u;
        __syncthreads();
    }
    if (t < SCAN_NB) g_part[t] = s[t] - v;
}

__global__ void __launch_bounds__(SCAN_CH) scan_write_kernel() {
    __shared__ int s[SCAN_CH];
    const int t = threadIdx.x;
    const int i = blockIdx.x * SCAN_CH + t;
    int v = (i < N_NODES) ? g_degin_i[i] : 0;
    s[t] = v;
    __syncthreads();
#pragma unroll
    for (int off = 1; off < SCAN_CH; off <<= 1) {
        int u = (t >= off) ? s[t - off] : 0;
        __syncthreads();
        s[t] += u;
        __syncthreads();
    }
    if (i < N_NODES) {
        int off = g_part[blockIdx.x] + s[t] - v;
        g_off[i] = off;
        g_cursor[i] = off;
    }
    if (i == 0) g_off[N_NODES] = N_EDGES;
}

__global__ void reorder_kernel(const int* __restrict__ src, const int* __restrict__ dst) {
    int e = blockIdx.x * blockDim.x + threadIdx.x;
    if (e >= N_EDGES) return;
    int pos = atomicAdd(&g_cursor[dst[e]], 1);
    g_esrc[pos] = src[e];
}

// ---------------------------------------------------------------------------
// Aggregation layer 1 + relu + GEMM2, fused (R11 structure, unchanged).
__global__ void __launch_bounds__(256) agg1_kernel(const float* __restrict__ b1,
                                                   const float* __restrict__ W2) {
    __shared__ float sW2[U * C];
    for (int i = threadIdx.x; i < U * C; i += 256) sW2[i] = W2[i];
    __syncthreads();

    const int n = (blockIdx.x * blockDim.x + threadIdx.x) >> 5;
    const int lane = threadIdx.x & 31;
    if (n >= N_NODES) return;
    const int slot = lane >> 3;
    const int q    = lane & 7;
    const int start = g_off[n], end = g_off[n + 1];

    float4 a4 = make_float4(0.f, 0.f, 0.f, 0.f);
    int e = start;
    while (e + 32 <= end) {
        int sv = g_esrc[e + lane];
#pragma unroll
        for (int i = 0; i < 8; i++) {
            int s = __shfl_sync(0xffffffffu, sv, 4 * i + slot);
            float4 v = *(const float4*)&g_h1[(size_t)s * U + 4 * q];
            a4.x += v.x; a4.y += v.y; a4.z += v.z; a4.w += v.w;
        }
        e += 32;
    }
    if (e < end) {
        const int rem = end - e;
        const int idx = e + lane;
        int sv = g_esrc[idx < end ? idx : end - 1];
        const int steps = (rem + 3) >> 2;
        for (int i = 0; i < steps; i++) {
            int s = __shfl_sync(0xffffffffu, sv, 4 * i + slot);
            float4 v = *(const float4*)&g_h1[(size_t)s * U + 4 * q];
            if (4 * i + slot < rem) { a4.x += v.x; a4.y += v.y; a4.z += v.z; a4.w += v.w; }
        }
    }
#pragma unroll
    for (int o = 8; o <= 16; o <<= 1) {
        a4.x += __shfl_xor_sync(0xffffffffu, a4.x, o);
        a4.y += __shfl_xor_sync(0xffffffffu, a4.y, o);
        a4.z += __shfl_xor_sync(0xffffffffu, a4.z, o);
        a4.w += __shfl_xor_sync(0xffffffffu, a4.w, o);
    }

    const int srcl = lane >> 2;
    float cx = __shfl_sync(0xffffffffu, a4.x, srcl);
    float cy = __shfl_sync(0xffffffffu, a4.y, srcl);
    float cz = __shfl_sync(0xffffffffu, a4.z, srcl);
    float cw = __shfl_sync(0xffffffffu, a4.w, srcl);
    const int comp = lane & 3;
    float accf = (comp == 0) ? cx : (comp == 1) ? cy : (comp == 2) ? cz : cw;

    const float v = fmaxf(accf * g_invin[n] + b1[lane], 0.f);

    float o0 = 0.f, o1 = 0.f;
#pragma unroll
    for (int k = 0; k < U; k++) {
        float h = __shfl_sync(0xffffffffu, v, k);
        o0 += h * sW2[k * C + lane];
        if (lane < 8) o1 += h * sW2[k * C + 32 + lane];
    }
    const float so = g_invout[n];
    g_h2[(size_t)n * C + lane] = o0 * so;
    if (lane < 8) g_h2[(size_t)n * C + 32 + lane] = o1 * so;
}

// ---------------------------------------------------------------------------
// Aggregation layer 2 (R11 structure, unchanged).
__global__ void agg2_kernel(float* __restrict__ out, const float* __restrict__ b2) {
    const int n = (blockIdx.x * blockDim.x + threadIdx.x) >> 5;
    const int lane = threadIdx.x & 31;
    if (n >= N_NODES) return;
    const int start = g_off[n], end = g_off[n + 1];
    const bool act = lane < 20;

    float ax = 0.f, ay = 0.f;
    int e = start;
    while (e + 32 <= end) {
        int sv = g_esrc[e + lane];
#pragma unroll
        for (int i = 0; i < 32; i++) {
            int s = __shfl_sync(0xffffffffu, sv, i);
            if (act) {
                float2 v = *(const float2*)&g_h2[(size_t)s * C + 2 * lane];
                ax += v.x; ay += v.y;
            }
        }
        e += 32;
    }
    if (e < end) {
        int rem = end - e;
        int sv = (lane < rem) ? g_esrc[e + lane] : 0;
        for (int i = 0; i < rem; i++) {
            int s = __shfl_sync(0xffffffffu, sv, i);
            if (act) {
                float2 v = *(const float2*)&g_h2[(size_t)s * C + 2 * lane];
                ax += v.x; ay += v.y;
            }
        }
    }

    const float inv = g_invin[n];
    const float NEG_INF = __int_as_float(0xff800000);
    float v0 = act ? (ax * inv + b2[2 * lane])     : NEG_INF;
    float v1 = act ? (ay * inv + b2[2 * lane + 1]) : NEG_INF;

    float m = fmaxf(v0, v1);
#pragma unroll
    for (int o = 16; o; o >>= 1) m = fmaxf(m, __shfl_xor_sync(0xffffffffu, m, o));
    float se = act ? (expf(v0 - m) + expf(v1 - m)) : 0.f;
#pragma unroll
    for (int o = 16; o; o >>= 1) se += __shfl_xor_sync(0xffffffffu, se, o);
    const float ls = logf(se);

    if (act) {
        float2 o;
        o.x = v0 - m - ls;
        o.y = v1 - m - ls;
        *(float2*)&out[(size_t)n * C + 2 * lane] = o;
    }
}

// ---------------------------------------------------------------------------
extern "C" void kernel_launch(void* const* d_in, const int* in_sizes, int n_in,
                              void* d_out, int out_size) {
    const float* x   = (const float*)d_in[0];
    const float* W1  = (const float*)d_in[1];
    const float* b1  = (const float*)d_in[2];
    const float* W2  = (const float*)d_in[3];
    const float* b2  = (const float*)d_in[4];
    const int*   src = (const int*)d_in[5];
    const int*   dst = (const int*)d_in[6];
    float* out = (float*)d_out;

    zero_deg_kernel<<<(N_NODES + 255) / 256, 256>>>();
    hist_kernel<<<(N_EDGES + 255) / 256, 256>>>(src, dst);
    invsqrt_kernel<<<(N_NODES + 255) / 256, 256>>>();
    gemm1_kernel<<<(N_NODES + TILE_N - 1) / TILE_N, 128>>>(x, W1);   // slot #4 -> profiled
    scan_part_kernel<<<SCAN_NB, SCAN_CH>>>();
    scan_mid_kernel<<<1, 256>>>();
    scan_write_kernel<<<SCAN_NB, SCAN_CH>>>();
    reorder_kernel<<<(N_EDGES + 255) / 256, 256>>>(src, dst);
    agg1_kernel<<<(N_NODES * 32 + 255) / 256, 256>>>(b1, W2);
    agg2_kernel<<<(N_NODES * 32 + 255) / 256, 256>>>(out, b2);
}